// round 1
// baseline (speedup 1.0000x reference)
#include <cuda_runtime.h>

// out[b, y, x] = in[b, y + dyi[b], x - dxi[b]] if in-bounds else 0
// B=1024, WIN=256, C=1, fp32.
// One thread per output float4. Output stores always aligned 128-bit.
// Input loads: vectorized when the shift keeps 16B alignment, scalar otherwise.

static constexpr int WIN  = 256;
static constexpr int WIN4 = WIN / 4;   // 64 float4 per row

__global__ __launch_bounds__(256) void translation_kernel(
    const float* __restrict__ in,
    const float* __restrict__ dx,
    const float* __restrict__ dy,
    float* __restrict__ out)
{
    int idx = blockIdx.x * blockDim.x + threadIdx.x;   // one float4 each
    int x4  = (idx & (WIN4 - 1)) << 2;                 // 0,4,...,252
    int row = idx >> 6;                                // b*WIN + y
    int b   = row >> 8;
    int y   = row & (WIN - 1);

    int dxi = (int)dx[b];                              // trunc toward zero == astype(int32)
    int dyi = (int)dy[b];

    int sy = y + dyi;
    float4 v = make_float4(0.f, 0.f, 0.f, 0.f);

    if (sy >= 0 && sy < WIN) {
        const float* src = in + (b << 16) + (sy << 8);
        int sx = x4 - dxi;
        if ((dxi & 3) == 0) {
            // aligned fast path: whole float4 in-bounds or fully masked per lane
            if (sx >= 0 && sx + 3 < WIN) {
                v = *reinterpret_cast<const float4*>(src + sx);
            } else {
                float* pv = reinterpret_cast<float*>(&v);
                #pragma unroll
                for (int i = 0; i < 4; i++) {
                    int s = sx + i;
                    if (s >= 0 && s < WIN) pv[i] = __ldg(src + s);
                }
            }
        } else {
            float* pv = reinterpret_cast<float*>(&v);
            #pragma unroll
            for (int i = 0; i < 4; i++) {
                int s = sx + i;
                if (s >= 0 && s < WIN) pv[i] = __ldg(src + s);
            }
        }
    }

    *reinterpret_cast<float4*>(out + (row << 8) + x4) = v;
}

extern "C" void kernel_launch(void* const* d_in, const int* in_sizes, int n_in,
                              void* d_out, int out_size)
{
    const float* in  = (const float*)d_in[0];
    const float* dx  = (const float*)d_in[1];
    const float* dy  = (const float*)d_in[2];
    float*       out = (float*)d_out;

    // total float4 elements = 1024*256*256/4 = 16,777,216
    int total4 = out_size / 4;
    int threads = 256;
    int blocks  = total4 / threads;   // 65536
    translation_kernel<<<blocks, threads>>>(in, dx, dy, out);
}

// round 2
// speedup vs baseline: 1.1214x; 1.1214x over previous
#include <cuda_runtime.h>

// out[b, y, x] = in[b, y + dyi[b], x - dxi[b]] if in-bounds else 0
// B=1024, WIN=256, C=1, fp32.
//
// Each thread produces 4 consecutive output float4 (16 floats) of one row.
// It loads the covering aligned window of 5 input float4 (clamped), then
// builds the shifted outputs with a uniform 4-way select on s = sx0 & 3.
// All GMEM transactions are 128-bit; MLP=5 wide loads per thread.

static constexpr int WIN = 256;

__global__ __launch_bounds__(256) void translation_kernel(
    const float4* __restrict__ in4,
    const float* __restrict__ dx,
    const float* __restrict__ dy,
    float4* __restrict__ out4)
{
    int idx    = blockIdx.x * blockDim.x + threadIdx.x;
    int tchunk = idx & 15;            // 16 threads per row, 16 floats each
    int row    = idx >> 4;            // b*256 + y
    int b      = row >> 8;
    int y      = row & (WIN - 1);

    int dxi = (int)dx[b];             // trunc toward zero == astype(int32)
    int dyi = (int)dy[b];
    int sy  = y + dyi;

    float4 o[4];
    o[0] = o[1] = o[2] = o[3] = make_float4(0.f, 0.f, 0.f, 0.f);

    if ((unsigned)sy < (unsigned)WIN) {
        const float4* src = in4 + (((b << 8) | sy) << 6);   // row base (64 float4/row)
        int x0  = tchunk << 4;        // first output float index of this chunk
        int sx0 = x0 - dxi;           // source float index of first output
        int q0  = sx0 >> 2;           // floor div 4 (arithmetic shift)
        int s   = sx0 & 3;            // uniform within block (x0 % 4 == 0)

        float4 a[5];
        #pragma unroll
        for (int i = 0; i < 5; i++) {
            int q = q0 + i;
            q = q < 0 ? 0 : (q > 63 ? 63 : q);   // clamp; garbage masked later
            a[i] = __ldg(src + q);
        }

        if (s == 0) {
            #pragma unroll
            for (int j = 0; j < 4; j++) o[j] = a[j];
        } else if (s == 1) {
            #pragma unroll
            for (int j = 0; j < 4; j++)
                o[j] = make_float4(a[j].y, a[j].z, a[j].w, a[j+1].x);
        } else if (s == 2) {
            #pragma unroll
            for (int j = 0; j < 4; j++)
                o[j] = make_float4(a[j].z, a[j].w, a[j+1].x, a[j+1].y);
        } else {
            #pragma unroll
            for (int j = 0; j < 4; j++)
                o[j] = make_float4(a[j].w, a[j+1].x, a[j+1].y, a[j+1].z);
        }

        // edge masking: component valid iff source index in [0, WIN)
        #pragma unroll
        for (int j = 0; j < 4; j++) {
            int st = sx0 + (j << 2);
            if ((unsigned)(st + 0) >= (unsigned)WIN) o[j].x = 0.f;
            if ((unsigned)(st + 1) >= (unsigned)WIN) o[j].y = 0.f;
            if ((unsigned)(st + 2) >= (unsigned)WIN) o[j].z = 0.f;
            if ((unsigned)(st + 3) >= (unsigned)WIN) o[j].w = 0.f;
        }
    }

    float4* dst = out4 + (row << 6) + (tchunk << 2);
    #pragma unroll
    for (int j = 0; j < 4; j++) dst[j] = o[j];
}

extern "C" void kernel_launch(void* const* d_in, const int* in_sizes, int n_in,
                              void* d_out, int out_size)
{
    const float4* in  = (const float4*)d_in[0];
    const float*  dx  = (const float*)d_in[1];
    const float*  dy  = (const float*)d_in[2];
    float4*       out = (float4*)d_out;

    // total threads = B*WIN*16 = 1024*256*16 = 4,194,304
    int threads = 256;
    int blocks  = (1024 * 256 * 16) / threads;   // 16384
    translation_kernel<<<blocks, threads>>>(in, dx, dy, out);
}

// round 3
// speedup vs baseline: 1.2362x; 1.1023x over previous
#include <cuda_runtime.h>

// out[b, y, x] = in[b, y + dyi[b], x - dxi[b]] if in-bounds else 0
// B=1024, WIN=256, C=1, fp32.
//
// One warp per row: 32 lanes x 2 float4 = 64 float4 = full row.
// Each lane loads exactly its 2 aligned float4 (zero load amplification);
// the 3rd chunk of the shifted window comes from __shfl_down of the next
// lane's first chunk. Lane 31 does one predicated extra load.
// Shift selector s = (x0 - dxi) & 3 is warp-uniform -> no divergence.

static constexpr int WIN = 256;

__global__ __launch_bounds__(256) void translation_kernel(
    const float4* __restrict__ in4,
    const float* __restrict__ dx,
    const float* __restrict__ dy,
    float4* __restrict__ out4)
{
    int idx  = blockIdx.x * blockDim.x + threadIdx.x;
    int lane = idx & 31;              // 32 lanes per row, 8 floats each
    int row  = idx >> 5;              // b*256 + y
    int b    = row >> 8;
    int y    = row & (WIN - 1);

    int dxi = (int)dx[b];             // trunc toward zero == astype(int32)
    int dyi = (int)dy[b];
    int sy  = y + dyi;
    bool rowok = (unsigned)sy < (unsigned)WIN;
    int syc = rowok ? sy : 0;         // clamped for addressing; masked below

    const float4* src = in4 + (((b << 8) | syc) << 6);   // 64 float4 per row

    int x0  = lane << 3;              // first output float index (0,8,...,248)
    int sx0 = x0 - dxi;               // source float index of first output
    int q0  = sx0 >> 2;               // arithmetic shift = floor div 4
    int s   = sx0 & 3;                // warp-uniform

    int c0 = q0     < 0 ? 0 : (q0     > 63 ? 63 : q0);
    int c1 = q0 + 1 < 0 ? 0 : (q0 + 1 > 63 ? 63 : q0 + 1);
    float4 a0 = __ldg(src + c0);
    float4 a1 = __ldg(src + c1);

    // a2 = next lane's a0 (lane 31 loads its own)
    float4 a2;
    a2.x = __shfl_down_sync(0xffffffffu, a0.x, 1);
    a2.y = __shfl_down_sync(0xffffffffu, a0.y, 1);
    a2.z = __shfl_down_sync(0xffffffffu, a0.z, 1);
    a2.w = __shfl_down_sync(0xffffffffu, a0.w, 1);
    if (lane == 31) {
        int c2 = q0 + 2 < 0 ? 0 : (q0 + 2 > 63 ? 63 : q0 + 2);
        a2 = __ldg(src + c2);
    }

    float4 o0, o1;
    if (s == 0) {
        o0 = a0;
        o1 = a1;
    } else if (s == 1) {
        o0 = make_float4(a0.y, a0.z, a0.w, a1.x);
        o1 = make_float4(a1.y, a1.z, a1.w, a2.x);
    } else if (s == 2) {
        o0 = make_float4(a0.z, a0.w, a1.x, a1.y);
        o1 = make_float4(a1.z, a1.w, a2.x, a2.y);
    } else {
        o0 = make_float4(a0.w, a1.x, a1.y, a1.z);
        o1 = make_float4(a1.w, a2.x, a2.y, a2.z);
    }

    // per-component edge masking (also kills invalid rows)
    unsigned base = rowok ? (unsigned)sx0 : 0xC0000000u;
    if (base + 0u >= (unsigned)WIN) o0.x = 0.f;
    if (base + 1u >= (unsigned)WIN) o0.y = 0.f;
    if (base + 2u >= (unsigned)WIN) o0.z = 0.f;
    if (base + 3u >= (unsigned)WIN) o0.w = 0.f;
    if (base + 4u >= (unsigned)WIN) o1.x = 0.f;
    if (base + 5u >= (unsigned)WIN) o1.y = 0.f;
    if (base + 6u >= (unsigned)WIN) o1.z = 0.f;
    if (base + 7u >= (unsigned)WIN) o1.w = 0.f;

    float4* dst = out4 + (row << 6) + (lane << 1);
    dst[0] = o0;
    dst[1] = o1;
}

extern "C" void kernel_launch(void* const* d_in, const int* in_sizes, int n_in,
                              void* d_out, int out_size)
{
    const float4* in  = (const float4*)d_in[0];
    const float*  dx  = (const float*)d_in[1];
    const float*  dy  = (const float*)d_in[2];
    float4*       out = (float4*)d_out;

    // total threads = B*WIN*32 = 8,388,608
    int threads = 256;
    int blocks  = (1024 * 256 * 32) / threads;   // 32768
    translation_kernel<<<blocks, threads>>>(in, dx, dy, out);
}